// round 6
// baseline (speedup 1.0000x reference)
#include <cuda_runtime.h>
#include <cuda_bf16.h>

#define N_TRIALS   8
#define T_TOTAL    600
#define N_NEURONS  30000
#define T_USE      500
#define N_SAMPLES  50
#define MAX_COUNT  200
#define N_BINS     16
#define EPS        1e-7f
#define SYNC_COST  10.0f

#define NCHUNK     7            // ceil(MAX_COUNT / 32)
#define FANO_BLOCKS 100         // 8 warps/block * 100 = 800 tasks

__constant__ int c_bins[N_BINS] = {1,1,2,3,4,6,9,13,18,26,38,55,78,113,162,234};

// Scratch (device globals: allocation is forbidden)
__device__ float        g_sel [N_SAMPLES * T_USE];     // sel[s][t]
__device__ float        g_fano[N_BINS * N_SAMPLES];    // per-(bin,sample) fano
__device__ unsigned int g_ticket;                      // last-block ticket (self-resets)

// ---------------------------------------------------------------------------
// Phase 1: gather. Block = one timestep t (grid 500, 512 thr = 16 warps).
// A warp owns one (s, t): its 32 lanes load 32 DIFFERENT ids at the SAME t,
// so each warp-LDG's addresses live in one 117KB spikes row (DRAM-row and
// L2 friendly), instead of spanning 3.8MB across t (previous layout).
// ids + per-sample counts cached in smem once per block.
// mask is prefix-form (arange < count) => lane-valid iff j < cnt.
// sample_ids arrives as int32 (JAX x64-disabled demotes int64 -> int32).
// ---------------------------------------------------------------------------
__global__ void __launch_bounds__(512)
gather_kernel(const float* __restrict__ spikes,
              const int*   __restrict__ trials,
              const int*   __restrict__ ids,
              const float* __restrict__ mask)
{
    __shared__ int s_ids[N_SAMPLES * MAX_COUNT];   // 40 KB
    __shared__ int s_cnt[N_SAMPLES];
    __shared__ int s_trial[N_SAMPLES];

    const int t    = blockIdx.x;
    const int tid  = threadIdx.x;
    const int lane = tid & 31;
    const int wid  = tid >> 5;

    if (tid < N_SAMPLES) { s_cnt[tid] = 0; s_trial[tid] = trials[tid]; }
    __syncthreads();

    // ids -> smem (coalesced)
    for (int i = tid; i < N_SAMPLES * MAX_COUNT; i += 512)
        s_ids[i] = ids[i];

    // per-sample effective counts via ballot over mask chunks
    for (int p = wid; p < N_SAMPLES * NCHUNK; p += 16) {
        const int s = p / NCHUNK, c = p % NCHUNK;
        const int j = c * 32 + lane;
        const float m = (j < MAX_COUNT) ? mask[s * MAX_COUNT + j] : 0.0f;
        const unsigned bal = __ballot_sync(0xffffffff, m != 0.0f);
        if (lane == 0 && bal) atomicAdd(&s_cnt[s], __popc(bal));
    }
    __syncthreads();

    for (int s = wid; s < N_SAMPLES; s += 16) {
        const int  cnt = s_cnt[s];
        const int* sid = s_ids + s * MAX_COUNT;
        const float* __restrict__ base =
            spikes + (size_t)s_trial[s] * ((size_t)T_TOTAL * N_NEURONS)
                   + (size_t)t * N_NEURONS;

        float acc = 0.0f;
        #pragma unroll
        for (int k = 0; k < NCHUNK; ++k) {
            const int  j  = k * 32 + lane;
            const bool on = (j < cnt);
            const int  id = on ? sid[j] : 0;
            const float v = on ? __ldg(base + id) : 0.0f;
            acc += v;
        }
        #pragma unroll
        for (int off = 16; off > 0; off >>= 1)
            acc += __shfl_down_sync(0xffffffff, acc, off);
        if (lane == 0)
            g_sel[s * T_USE + t] = acc;
    }
}

// ---------------------------------------------------------------------------
// Phase 2: one warp per (bin, sample) task; 100 blocks x 8 warps = 800 tasks.
// Warp streams its sample's 500-float row (L2-hot) with single-pass
// sum / sum-of-squares. Last block (ticket) computes the final MSE scalar
// and resets the ticket for the next graph replay.
// ---------------------------------------------------------------------------
__global__ void __launch_bounds__(256)
fano_kernel(const float* __restrict__ exp_fanos, float* __restrict__ out)
{
    __shared__ bool s_last;

    const int tid  = threadIdx.x;
    const int lane = tid & 31;
    const int wid  = tid >> 5;
    const int task = blockIdx.x * 8 + wid;     // 0 .. 799
    const int b    = task / N_SAMPLES;
    const int s    = task % N_SAMPLES;
    const int bs   = c_bins[b];
    const int nb   = T_USE / bs;
    const float* __restrict__ row = g_sel + s * T_USE;

    float sum = 0.0f, sumsq = 0.0f;
    for (int k = lane; k < nb; k += 32) {
        const float* rk = row + k * bs;
        float c = 0.0f;
        int u = 0;
        for (; u + 4 <= bs; u += 4) {
            float a0 = __ldg(rk + u),     a1 = __ldg(rk + u + 1);
            float a2 = __ldg(rk + u + 2), a3 = __ldg(rk + u + 3);
            c += (a0 + a1) + (a2 + a3);
        }
        for (; u < bs; ++u) c += __ldg(rk + u);
        sum   += c;
        sumsq += c * c;
    }
    #pragma unroll
    for (int off = 16; off > 0; off >>= 1) {
        sum   += __shfl_down_sync(0xffffffff, sum,   off);
        sumsq += __shfl_down_sync(0xffffffff, sumsq, off);
    }
    if (lane == 0) {
        const float mean = sum / (float)nb;
        const float var  = sumsq / (float)nb - mean * mean;
        g_fano[task] = var / fmaxf(mean, EPS);
    }

    // last-block reduction -> scalar loss
    __threadfence();
    __syncthreads();
    if (tid == 0) {
        unsigned int old = atomicAdd(&g_ticket, 1u);
        s_last = (old == FANO_BLOCKS - 1);
    }
    __syncthreads();

    if (s_last) {
        if (tid == 0) g_ticket = 0;        // reset for next graph replay
        if (wid == 0) {
            float d2 = 0.0f;
            if (lane < N_BINS) {
                float fsum = 0.0f;
                for (int q = 0; q < N_SAMPLES; ++q)
                    fsum += g_fano[lane * N_SAMPLES + q];
                const float fm = fsum / (float)N_SAMPLES;
                const float d  = exp_fanos[lane] - fm;
                d2 = d * d;
            }
            #pragma unroll
            for (int off = 16; off > 0; off >>= 1)
                d2 += __shfl_down_sync(0xffffffff, d2, off);
            if (lane == 0)
                out[0] = SYNC_COST * (d2 / (float)N_BINS);
        }
    }
}

// ---------------------------------------------------------------------------
// Inputs (metadata order):
//   0: spikes float32 [8,600,30000]   1: experimental_fanos_mean float32 [16]
//   2: sample_trials int32 [50]       3: sample_ids int32 [50,200]
//   4: sample_mask float32 [50,200]   out: float32 scalar
// ---------------------------------------------------------------------------
extern "C" void kernel_launch(void* const* d_in, const int* in_sizes, int n_in,
                              void* d_out, int out_size)
{
    const float* spikes = (const float*)d_in[0];
    const float* expf_  = (const float*)d_in[1];
    const int*   trials = (const int*)d_in[2];
    const int*   ids    = (const int*)d_in[3];
    const float* mask   = (const float*)d_in[4];
    float*       out    = (float*)d_out;

    gather_kernel<<<T_USE, 512>>>(spikes, trials, ids, mask);
    fano_kernel<<<FANO_BLOCKS, 256>>>(expf_, out);
}

// round 7
// speedup vs baseline: 1.3549x; 1.3549x over previous
#include <cuda_runtime.h>
#include <cuda_bf16.h>

#define N_TRIALS   8
#define T_TOTAL    600
#define N_NEURONS  30000
#define T_USE      500
#define N_SAMPLES  50
#define MAX_COUNT  200
#define N_BINS     16
#define EPS        1e-7f
#define SYNC_COST  10.0f

#define NJ          8                 // per-sample id chunks (dynamic split of [0,cnt))
#define JMAX        32                // >= ceil(MAX_COUNT/NJ) = 25
#define FANO_BLOCKS 100               // (sample, bin-half): 50 x 2

__constant__ int c_bins[N_BINS] = {1,1,2,3,4,6,9,13,18,26,38,55,78,113,162,234};

// Scratch (device globals: allocation is forbidden)
__device__ float        g_part[NJ * N_SAMPLES * T_USE];  // partial gather sums
__device__ float        g_fano[N_BINS * N_SAMPLES];      // per-(bin,sample) fano
__device__ unsigned int g_ticket;                        // last-block ticket (self-resets)

// ---------------------------------------------------------------------------
// Phase 1: gather partial sums. Block = (sample, j-chunk); each of the 128
// threads owns FOUR timesteps (t, t+128, t+256, t+384) -> fat, long-lived
// CTAs (amortizes cross-CTA L1tex-queue contention) with 8 independent
// scattered LDGs in flight per thread (2 ids x 4 t-streams per iteration).
// mask is prefix-form (arange < count) => effective count = sum(mask);
// ids[0:cnt] are exactly the active ids. j-chunks split [0,cnt) evenly.
// sample_ids arrives as int32 (JAX x64-disabled demotes int64 -> int32).
// ---------------------------------------------------------------------------
__global__ void __launch_bounds__(128)
gather_kernel(const float* __restrict__ spikes,
              const int*   __restrict__ trials,
              const int*   __restrict__ ids,
              const float* __restrict__ mask)
{
    __shared__ int s_ids[JMAX];
    __shared__ int s_cnt;

    const int s   = blockIdx.x;
    const int jc  = blockIdx.z;
    const int tid = threadIdx.x;

    if (tid == 0) s_cnt = 0;
    __syncthreads();

    int local = 0;
    #pragma unroll
    for (int j = tid; j < MAX_COUNT; j += 128)
        if (mask[s * MAX_COUNT + j] != 0.0f) local++;
    if (local) atomicAdd(&s_cnt, local);
    __syncthreads();

    const int cnt = s_cnt;
    const int lo  = (jc * cnt) / NJ;
    const int m   = ((jc + 1) * cnt) / NJ - lo;    // <= 25
    if (tid < m)
        s_ids[tid] = ids[s * MAX_COUNT + lo + tid];
    __syncthreads();

    const size_t trialOff = (size_t)trials[s] * ((size_t)T_TOTAL * N_NEURONS);

    const int t0 = tid;            // < 500 always
    const int t1 = tid + 128;      // < 500 always
    const int t2 = tid + 256;      // <= 383, always valid
    const int t3 = tid + 384;      // valid iff tid < 116
    const bool v3 = (t3 < T_USE);
    const int t3c = v3 ? t3 : 0;

    const float* __restrict__ b0 = spikes + trialOff + (size_t)t0  * N_NEURONS;
    const float* __restrict__ b1 = spikes + trialOff + (size_t)t1  * N_NEURONS;
    const float* __restrict__ b2 = spikes + trialOff + (size_t)t2  * N_NEURONS;
    const float* __restrict__ b3 = spikes + trialOff + (size_t)t3c * N_NEURONS;

    float a0 = 0.0f, a1 = 0.0f, a2 = 0.0f, a3 = 0.0f;
    int j = 0;
    for (; j + 2 <= m; j += 2) {
        const int idA = s_ids[j];
        const int idB = s_ids[j + 1];
        // 8 independent scattered loads in flight
        float x0 = __ldg(b0 + idA), x1 = __ldg(b1 + idA);
        float x2 = __ldg(b2 + idA), x3 = __ldg(b3 + idA);
        float y0 = __ldg(b0 + idB), y1 = __ldg(b1 + idB);
        float y2 = __ldg(b2 + idB), y3 = __ldg(b3 + idB);
        a0 += x0 + y0;  a1 += x1 + y1;
        a2 += x2 + y2;  a3 += x3 + y3;
    }
    if (j < m) {
        const int idA = s_ids[j];
        a0 += __ldg(b0 + idA);  a1 += __ldg(b1 + idA);
        a2 += __ldg(b2 + idA);  a3 += __ldg(b3 + idA);
    }

    float* __restrict__ dst = g_part + (jc * N_SAMPLES + s) * T_USE;
    dst[t0] = a0;
    dst[t1] = a1;
    dst[t2] = a2;
    if (v3) dst[t3] = a3;
}

// ---------------------------------------------------------------------------
// Phase 2: block = (sample, bin-half); 100 blocks x 256 threads.
//   - combine the sample's NJ partials into a 500-float smem row with a
//     wide coalesced load (fixed order -> deterministic)
//   - 8 warps: warp w computes bin (half*8 + w) from smem (single-pass
//     sum / sum-of-squares, warp shfl reduce)
//   - last block (ticket) computes per-bin means, MSE, scales, writes out,
//     and resets the ticket for the next graph replay.
// ---------------------------------------------------------------------------
__global__ void __launch_bounds__(256)
fano_kernel(const float* __restrict__ exp_fanos, float* __restrict__ out)
{
    __shared__ float s_row[T_USE];
    __shared__ bool  s_last;

    const int s    = blockIdx.x >> 1;          // sample
    const int half = blockIdx.x & 1;           // bin half (0: bins 0-7, 1: 8-15)
    const int tid  = threadIdx.x;
    const int lane = tid & 31;
    const int wid  = tid >> 5;

    // combine partials into smem row (coalesced over i, unrolled over chunks)
    for (int i = tid; i < T_USE; i += 256) {
        float v = 0.0f;
        #pragma unroll
        for (int c = 0; c < NJ; ++c)
            v += g_part[(c * N_SAMPLES + s) * T_USE + i];
        s_row[i] = v;
    }
    __syncthreads();

    {
        const int b  = half * 8 + wid;
        const int bs = c_bins[b];
        const int nb = T_USE / bs;

        float sum = 0.0f, sumsq = 0.0f;
        for (int k = lane; k < nb; k += 32) {
            const float* rk = s_row + k * bs;
            float c = 0.0f;
            int u = 0;
            for (; u + 4 <= bs; u += 4) {
                float a0 = rk[u], a1 = rk[u+1], a2 = rk[u+2], a3 = rk[u+3];
                c += (a0 + a1) + (a2 + a3);
            }
            for (; u < bs; ++u) c += rk[u];
            sum   += c;
            sumsq += c * c;
        }
        #pragma unroll
        for (int off = 16; off > 0; off >>= 1) {
            sum   += __shfl_down_sync(0xffffffff, sum,   off);
            sumsq += __shfl_down_sync(0xffffffff, sumsq, off);
        }
        if (lane == 0) {
            const float mean = sum / (float)nb;
            const float var  = sumsq / (float)nb - mean * mean;
            g_fano[b * N_SAMPLES + s] = var / fmaxf(mean, EPS);
        }
    }

    // last-block reduction -> scalar loss
    __threadfence();
    __syncthreads();
    if (tid == 0) {
        unsigned int old = atomicAdd(&g_ticket, 1u);
        s_last = (old == FANO_BLOCKS - 1);
    }
    __syncthreads();

    if (s_last) {
        if (tid == 0) g_ticket = 0;        // reset for next graph replay
        if (wid == 0) {
            float d2 = 0.0f;
            if (lane < N_BINS) {
                float fsum = 0.0f;
                for (int q = 0; q < N_SAMPLES; ++q)
                    fsum += g_fano[lane * N_SAMPLES + q];
                const float fm = fsum / (float)N_SAMPLES;
                const float d  = exp_fanos[lane] - fm;
                d2 = d * d;
            }
            #pragma unroll
            for (int off = 16; off > 0; off >>= 1)
                d2 += __shfl_down_sync(0xffffffff, d2, off);
            if (lane == 0)
                out[0] = SYNC_COST * (d2 / (float)N_BINS);
        }
    }
}

// ---------------------------------------------------------------------------
// Inputs (metadata order):
//   0: spikes float32 [8,600,30000]   1: experimental_fanos_mean float32 [16]
//   2: sample_trials int32 [50]       3: sample_ids int32 [50,200]
//   4: sample_mask float32 [50,200]   out: float32 scalar
// ---------------------------------------------------------------------------
extern "C" void kernel_launch(void* const* d_in, const int* in_sizes, int n_in,
                              void* d_out, int out_size)
{
    const float* spikes = (const float*)d_in[0];
    const float* expf_  = (const float*)d_in[1];
    const int*   trials = (const int*)d_in[2];
    const int*   ids    = (const int*)d_in[3];
    const float* mask   = (const float*)d_in[4];
    float*       out    = (float*)d_out;

    dim3 grid(N_SAMPLES, 1, NJ);
    gather_kernel<<<grid, 128>>>(spikes, trials, ids, mask);
    fano_kernel<<<FANO_BLOCKS, 256>>>(expf_, out);
}